// round 10
// baseline (speedup 1.0000x reference)
#include <cuda_runtime.h>
#include <math.h>

#define NQ 12
#define TPB 256
#define NB 128

typedef unsigned long long u64;

__device__ __forceinline__ u64 pk(float lo, float hi) {
    u64 r;
    asm("mov.b64 %0,{%1,%2};" : "=l"(r)
        : "r"(__float_as_uint(lo)), "r"(__float_as_uint(hi)));
    return r;
}
__device__ __forceinline__ void upk(u64 v, float& lo, float& hi) {
    unsigned a, b;
    asm("mov.b64 {%0,%1},%2;" : "=r"(a), "=r"(b) : "l"(v));
    lo = __uint_as_float(a); hi = __uint_as_float(b);
}
__device__ __forceinline__ u64 sp(float f) { return pk(f, f); }
__device__ __forceinline__ u64 f2(u64 a, u64 b, u64 c) {
    u64 d;
    asm("fma.rn.f32x2 %0,%1,%2,%3;" : "=l"(d) : "l"(a), "l"(b), "l"(c));
    return d;
}
__device__ __forceinline__ u64 m2(u64 a, u64 b) {
    u64 d;
    asm("mul.rn.f32x2 %0,%1,%2;" : "=l"(d) : "l"(a), "l"(b));
    return d;
}
__device__ __forceinline__ u64 swp(u64 v) {
    float l, h; upk(v, l, h); return pk(h, l);
}

__device__ __forceinline__ float2 cmulc(float2 x, float2 y) {
    return make_float2(x.x * y.x - x.y * y.y, x.x * y.y + x.y * y.x);
}

__device__ __forceinline__ float gelu_f(float x) {
    return 0.5f * x * (1.0f + erff(x * 0.7071067811865476f));
}

// Composed CNOT-ring permutation. Qubit w at bit (11-w). GF(2)-linear.
__device__ __forceinline__ int permdst(int idx) {
    int y = idx;
    y ^= y >> 1; y ^= y >> 2; y ^= y >> 4; y ^= y >> 8;
    return (y & 0x7FF) | (((y ^ (idx >> 11)) & 1) << 11);
}

// ---- symmetric-form gates: float4 m = (U0.x,U0.y,U1.x,U1.y),
//      U11 = conj(U00), U10 = (-U01.x, U01.y). ----

__device__ __forceinline__ void kgate(u64* SX, u64* SY, float4 m, int rb)
{
    u64 g0x = sp(m.x),  g0y = sp(m.y), g0yn = sp(-m.y);
    u64 g1x = sp(m.z),  g1xn = sp(-m.z);
    u64 g1y = sp(m.w),  g1yn = sp(-m.w);
    #pragma unroll
    for (int k = 0; k < 8; k++) {
        if (!((k >> rb) & 1)) {
            const int k1 = k | (1 << rb);
            u64 X0 = SX[k], Y0 = SY[k], X1 = SX[k1], Y1 = SY[k1];
            SX[k]  = f2(g1yn, Y1, f2(g1x, X1, f2(g0yn, Y0, m2(g0x, X0))));
            SY[k]  = f2(g1y,  X1, f2(g1x, Y1, f2(g0y,  X0, m2(g0x, Y0))));
            SX[k1] = f2(g0y,  Y1, f2(g0x, X1, f2(g1yn, Y0, m2(g1xn, X0))));
            SY[k1] = f2(g0yn, X1, f2(g0x, Y1, f2(g1y,  X0, m2(g1xn, Y0))));
        }
    }
}

__device__ __forceinline__ void pgate(u64* SX, u64* SY, float4 m)
{
    u64 Dx  = sp(m.x);
    u64 Dy  = pk(m.y, -m.y), Dyn = pk(-m.y, m.y);
    u64 Ox  = pk(m.z, -m.z);
    u64 Oy  = sp(m.w), Oyn = sp(-m.w);
    #pragma unroll
    for (int k = 0; k < 8; k++) {
        u64 sX = swp(SX[k]), sY = swp(SY[k]);
        u64 nX = f2(Oyn, sY, f2(Ox, sX, f2(Dyn, SY[k], m2(Dx, SX[k]))));
        u64 nY = f2(Oy,  sX, f2(Ox, sY, f2(Dy,  SX[k], m2(Dx, SY[k]))));
        SX[k] = nX; SY[k] = nY;
    }
}

__device__ __forceinline__ void sgate(u64* SX, u64* SY, float4 m, int p, int lane)
{
    const int sb = (lane >> p) & 1;
    float dY = sb ? -m.y : m.y;
    float oX = sb ? -m.z : m.z;
    u64 gdx = sp(m.x), gdy = sp(dY), gdyn = sp(-dY);
    u64 gox = sp(oX),  goy = sp(m.w), goyn = sp(-m.w);
    #pragma unroll
    for (int k = 0; k < 8; k++) {
        float xl, xh, yl, yh;
        upk(SX[k], xl, xh); upk(SY[k], yl, yh);
        float oxl = __shfl_xor_sync(~0u, xl, 1 << p);
        float oxh = __shfl_xor_sync(~0u, xh, 1 << p);
        float oyl = __shfl_xor_sync(~0u, yl, 1 << p);
        float oyh = __shfl_xor_sync(~0u, yh, 1 << p);
        u64 OX = pk(oxl, oxh), OY = pk(oyl, oyh);
        u64 nX = f2(goyn, OY, f2(gox, OX, f2(gdyn, SY[k], m2(gdx, SX[k]))));
        u64 nY = f2(goy,  OX, f2(gox, OY, f2(gdy,  SX[k], m2(gdx, SY[k]))));
        SX[k] = nX; SY[k] = nY;
    }
}

// ---- RT pieces (R9-validated address maps) ----

__device__ __forceinline__ void perm_scatter(const u64* SX, const u64* SY,
    float2* fb, int dt, unsigned czm0, unsigned czm1, unsigned czsel)
{
    #pragma unroll
    for (int k = 0; k < 8; k++) {
        int d0 = dt ^ permdst(k << 5);
        float xl, xh, yl, yh;
        upk(SX[k], xl, xh); upk(SY[k], yl, yh);
        unsigned g0 = ((czm0 >> k) & czsel) << 31;
        unsigned g1 = ((czm1 >> k) & czsel) << 31;
        xl = __uint_as_float(__float_as_uint(xl) ^ g0);
        yl = __uint_as_float(__float_as_uint(yl) ^ g0);
        xh = __uint_as_float(__float_as_uint(xh) ^ g1);
        yh = __uint_as_float(__float_as_uint(yh) ^ g1);
        fb[d0] = make_float2(xl, yl);
        fb[d0 ^ 0x81F] = make_float2(xh, yh);
    }
}

__device__ __forceinline__ void perm_gather(u64* SX, u64* SY,
    const float2* fb, float4 mg, int tid)
{
    const int sbq = tid & 1;
    float dyv = sbq ? -mg.y : mg.y;
    float oxv = sbq ? -mg.z : mg.z;
    float2 gd = make_float2(mg.x, dyv);
    float2 go = make_float2(oxv, mg.w);
    float2 Cl = sbq ? go : gd;
    float2 Ch = sbq ? gd : go;
    u64 clr = sp(Cl.x), cli = sp(Cl.y), cln = sp(-Cl.y);
    u64 chr = sp(Ch.x), chi_ = sp(Ch.y), chn = sp(-Ch.y);
    const float4* F4 = (const float4*)fb;
    const int gbase = tid >> 1;
    #pragma unroll
    for (int k = 0; k < 8; k++) {
        int i4 = (k << 7) | gbase;
        float4 va = F4[i4];
        float4 vb = F4[i4 | 0x400];
        u64 Xl = pk(va.x, vb.x), Yl = pk(va.y, vb.y);
        u64 Xh = pk(va.z, vb.z), Yh = pk(va.w, vb.w);
        SX[k] = f2(chn, Yh, f2(chr, Xh, f2(cln, Yl, m2(clr, Xl))));
        SY[k] = f2(chi_, Xh, f2(chr, Yh, f2(cli, Xl, m2(clr, Yl))));
    }
}

__device__ __forceinline__ void tr_scatter(const u64* SX, const u64* SY,
    float2* fb, int stid)
{
    #pragma unroll
    for (int k = 0; k < 8; k++) {
        int s0 = (k << 8) | stid;
        float xl, xh, yl, yh;
        upk(SX[k], xl, xh); upk(SY[k], yl, yh);
        fb[s0] = make_float2(xl, yl);
        fb[s0 | 0x800] = make_float2(xh, yh);
    }
}

__device__ __forceinline__ void tr_gather(u64* SX, u64* SY,
    const float2* fb, float4 mg, int tid, int gb4T)
{
    const int sbq = (tid >> 3) & 1;
    float dyv = sbq ? -mg.y : mg.y;
    float oxv = sbq ? -mg.z : mg.z;
    float2 gd = make_float2(mg.x, dyv);
    float2 go = make_float2(oxv, mg.w);
    float2 Cl = sbq ? go : gd;
    float2 Ch = sbq ? gd : go;
    u64 clr = sp(Cl.x), cli = sp(Cl.y), cln = sp(-Cl.y);
    u64 chr = sp(Ch.x), chi_ = sp(Ch.y), chn = sp(-Ch.y);
    const float4* F4 = (const float4*)fb;
    #pragma unroll
    for (int k = 0; k < 8; k++) {
        int i4 = (k << 4) | gb4T;
        float4 va = F4[i4];
        float4 vb = F4[i4 + 8];
        u64 Xl = pk(va.x, vb.x), Yl = pk(va.y, vb.y);
        u64 Xh = pk(va.z, vb.z), Yh = pk(va.w, vb.w);
        SX[k] = f2(chn, Yh, f2(chr, Xh, f2(cln, Yl, m2(clr, Xl))));
        SY[k] = f2(chi_, Xh, f2(chr, Yh, f2(cli, Xl, m2(clr, Yl))));
    }
}

__global__ void __launch_bounds__(TPB, 1)
qpu_kernel(const float* __restrict__ x,
           const float* __restrict__ W1, const float* __restrict__ b1,
           const float* __restrict__ g_ln, const float* __restrict__ b_ln,
           const float* __restrict__ W2, const float* __restrict__ b2,
           const float* __restrict__ W3, const float* __restrict__ b3,
           const float* __restrict__ qw,
           const float* __restrict__ W4, const float* __restrict__ b4,
           const float* __restrict__ W5, const float* __restrict__ b5,
           float* __restrict__ out)
{
    // dynamic: 4 float2 buffers of 4096 (2 samples x ping-pong) = 128 KB
    extern __shared__ float2 fsm[];
    __shared__ __align__(16) float xrow[2][256];
    __shared__ __align__(16) float h1s[2][128];
    __shared__ __align__(16) float hns[2][128];
    __shared__ __align__(16) float h2s[2][64];
    __shared__ float4 Mraw[5][NQ];        // shared raw gates, layers 1..5
    __shared__ float4 Mf[2][3][NQ];       // RY-folded gates for layers 1,3,5
    __shared__ float2 v0s[2][NQ], v1s[2][NQ];
    __shared__ float cqs[2][NQ], sqs[2][NQ];
    __shared__ float red0[8], red1[8];
    __shared__ float stats[2][2];
    __shared__ float wz[8][6];
    __shared__ float qv[6];
    __shared__ float h4s[2][32];

    const int tid = threadIdx.x;
    const int bidx = blockIdx.x;
    const int lane = tid & 31, w = tid >> 5;

    xrow[0][tid] = x[(2 * bidx) * 256 + tid];
    xrow[1][tid] = x[(2 * bidx + 1) * 256 + tid];
    __syncthreads();

    // ---- h1 for both samples (256 threads = 2 x 128 outputs) ----
    {
        int s = tid >> 7, o = tid & 127;
        const float4* wr = (const float4*)(W1 + o * 256);
        const float4* xr = (const float4*)xrow[s];
        float acc0 = 0.f, acc1 = 0.f;
        #pragma unroll 8
        for (int k = 0; k < 64; k += 2) {
            float4 wv = wr[k], xv = xr[k];
            acc0 = fmaf(wv.x, xv.x, acc0); acc0 = fmaf(wv.y, xv.y, acc0);
            acc0 = fmaf(wv.z, xv.z, acc0); acc0 = fmaf(wv.w, xv.w, acc0);
            float4 w2_ = wr[k + 1], xv2 = xr[k + 1];
            acc1 = fmaf(w2_.x, xv2.x, acc1); acc1 = fmaf(w2_.y, xv2.y, acc1);
            acc1 = fmaf(w2_.z, xv2.z, acc1); acc1 = fmaf(w2_.w, xv2.w, acc1);
        }
        h1s[s][o] = gelu_f(acc0 + acc1 + b1[o]);
    }
    __syncthreads();

    // ---- layernorm (both samples; warps 0-3 s0, warps 4-7 s1) ----
    {
        int s = tid >> 7, o = tid & 127;
        float v = h1s[s][o];
        float su = v, ss = v * v;
        #pragma unroll
        for (int o2 = 16; o2; o2 >>= 1) {
            su += __shfl_xor_sync(~0u, su, o2);
            ss += __shfl_xor_sync(~0u, ss, o2);
        }
        if (lane == 0) { red0[w] = su; red1[w] = ss; }
    }
    __syncthreads();
    if ((tid & 127) == 0) {
        int s = tid >> 7;
        float su = 0.f, ss = 0.f;
        #pragma unroll
        for (int i = 0; i < 4; i++) { su += red0[s * 4 + i]; ss += red1[s * 4 + i]; }
        float mu = su * (1.f / 128.f);
        float var = ss * (1.f / 128.f) - mu * mu;
        stats[s][0] = mu; stats[s][1] = rsqrtf(var + 1e-5f);
    }
    __syncthreads();
    {
        int s = tid >> 7, o = tid & 127;
        hns[s][o] = (h1s[s][o] - stats[s][0]) * stats[s][1] * g_ln[o] + b_ln[o];
    }
    __syncthreads();

    // ---- h2 (128 threads = 2 x 64 outputs); overlap: raw gate tables ----
    if (tid < 128) {
        int s = tid >> 6, o = tid & 63;
        const float4* wr = (const float4*)(W2 + o * 128);
        const float4* hr = (const float4*)hns[s];
        float acc = 0.f;
        #pragma unroll 8
        for (int k = 0; k < 32; k++) {
            float4 wv = wr[k], hv = hr[k];
            acc = fmaf(wv.x, hv.x, acc); acc = fmaf(wv.y, hv.y, acc);
            acc = fmaf(wv.z, hv.z, acc); acc = fmaf(wv.w, hv.w, acc);
        }
        h2s[s][o] = gelu_f(acc + b2[o]);
    } else if (tid < 188) {
        int idx = tid - 128;                 // 0..59
        int L = idx / 12 + 1, q = idx - (L - 1) * 12;
        const float* wp = qw + (L * NQ + q) * 3;
        float w0 = wp[0], w1 = wp[1], w2v = wp[2];
        float sh, ch; sincosf(0.5f * w1, &sh, &ch);
        float sa, ca; sincosf(0.5f * (w0 + w2v), &sa, &ca);
        float sb, cb; sincosf(0.5f * (w0 - w2v), &sb, &cb);
        Mraw[L - 1][q] = make_float4(ch * ca, -ch * sa, -sh * cb, -sh * sb);
    }
    __syncthreads();

    // ---- xq / encoding per sample (24 threads) ----
    if (tid < 24) {
        int s = tid / 12, q = tid % 12;
        const float* wr = W3 + q * 64;
        float acc = 0.f;
        #pragma unroll
        for (int k = 0; k < 64; k++) acc = fmaf(wr[k], h2s[s][k], acc);
        float xqv = tanhf(acc + b3[q]);
        float e = xqv * 9.869604401089358f;   // pi^2
        float se, ce; sincosf(0.5f * e, &se, &ce);
        const float* wp = qw + q * 3;
        float w0 = wp[0], w1 = wp[1], w2v = wp[2];
        float sh, ch; sincosf(0.5f * w1, &sh, &ch);
        float sa, ca; sincosf(0.5f * (w0 + w2v), &sa, &ca);
        float sb, cb; sincosf(0.5f * (w0 - w2v), &sb, &cb);
        float2 u00 = make_float2(ch * ca, -ch * sa);
        float2 u01 = make_float2(-sh * cb, -sh * sb);
        float2 u10 = make_float2(sh * cb, -sh * sb);
        float2 u11 = make_float2(ch * ca, ch * sa);
        v0s[s][q] = make_float2(u00.x * ce + u01.x * se, u00.y * ce + u01.y * se);
        v1s[s][q] = make_float2(u10.x * ce + u11.x * se, u10.y * ce + u11.y * se);
        float s4, c4; sincosf(0.25f * e, &s4, &c4);
        cqs[s][q] = c4; sqs[s][q] = s4;
    }
    __syncthreads();

    // ---- fold RY(enc/2) into odd layers per sample (72 threads) ----
    if (tid < 72) {
        int s = tid / 36, r = tid % 36;
        int li = r / 12, q = r % 12;           // li: 0,1,2 -> layers 1,3,5
        float4 m = Mraw[2 * li][q];
        float cf = cqs[s][q], sf = sqs[s][q];
        Mf[s][li][q] = make_float4(m.x * cf + m.z * sf,  m.y * cf + m.w * sf,
                                   -m.x * sf + m.z * cf, -m.y * sf + m.w * cf);
    }
    __syncthreads();

    // ============ two statevectors per thread ============
    u64 AX[8], AY[8], BX[8], BY[8];
    const int tb = (tid & 0xF) | ((tid >> 5) << 8) | (((tid >> 4) & 1) << 11);
    const int dt = permdst(tb);
    const int stid = (tid & ~9) | ((tid & 1) << 3) | ((tid >> 3) & 1);
    const int sgtb = (tb & ~9) | ((tb & 1) << 3) | ((tb >> 3) & 1);
    const int gb4T = (sgtb & ~1) >> 1;

    unsigned czm0 = 0, czm1 = 0;
    #pragma unroll
    for (int k = 0; k < 8; k++) {
        int d0 = dt ^ permdst(k << 5);
        int d1 = d0 ^ 0x81F;
        czm0 |= ((unsigned)__popc((d0 & (d0 >> 2)) & 0x2AA) & 1u) << k;
        czm1 |= ((unsigned)__popc((d1 & (d1 >> 2)) & 0x2AA) & 1u) << k;
    }

    // ---- init product states in T layout (layer-0 gates folded) ----
    #pragma unroll
    for (int s = 0; s < 2; s++) {
        const float2* v0 = v0s[s];
        const float2* v1 = v1s[s];
        float2 cm = (tid & 1) ? v1[11] : v0[11];
        cm = cmulc(cm, (tid & 2) ? v1[10] : v0[10]);
        cm = cmulc(cm, (tid & 4) ? v1[9] : v0[9]);
        cm = cmulc(cm, (tid & 8) ? v1[8] : v0[8]);
        cm = cmulc(cm, ((tid >> 4) & 1) ? v1[0] : v0[0]);
        cm = cmulc(cm, ((tid >> 5) & 1) ? v1[3] : v0[3]);
        cm = cmulc(cm, ((tid >> 6) & 1) ? v1[2] : v0[2]);
        cm = cmulc(cm, ((tid >> 7) & 1) ? v1[1] : v0[1]);
        float2 q7a = v0[7], q7b = v1[7];
        u64* SX = s ? BX : AX;
        u64* SY = s ? BY : AY;
        #pragma unroll
        for (int k = 0; k < 8; k++) {
            float2 a = cm;
            a = cmulc(a, (k & 1) ? v1[6] : v0[6]);
            a = cmulc(a, (k & 2) ? v1[5] : v0[5]);
            a = cmulc(a, (k & 4) ? v1[4] : v0[4]);
            float2 lo = cmulc(a, q7a);
            float2 hi = cmulc(a, q7b);
            SX[k] = pk(lo.x, hi.x);
            SY[k] = pk(lo.y, hi.y);
        }
    }

    float2* bufA = fsm;           // A ping-pong: fsm[0], fsm[4096]
    float2* bufB = fsm + 8192;    // B ping-pong: fsm[8192], fsm[12288]
    int b = 0;

    // ---- layer-0 perm (no CZ); gather folds layer-1 q11 (per sample) ----
    perm_scatter(AX, AY, bufA + b * 4096, dt, czm0, czm1, 0u);
    perm_scatter(BX, BY, bufB + b * 4096, dt, czm0, czm1, 0u);
    __syncthreads();
    perm_gather(AX, AY, bufA + b * 4096, Mf[0][0][11], tid);
    perm_gather(BX, BY, bufB + b * 4096, Mf[1][0][11], tid);
    b ^= 1;

    // ---- layers 1..5 ----
    for (int l = 1; l < 6; l++) {
        const float4* MA = (l & 1) ? Mf[0][(l - 1) >> 1] : Mraw[l - 1];
        const float4* MB = (l & 1) ? Mf[1][(l - 1) >> 1] : Mraw[l - 1];

        // C phase (q11 folded at previous gather)
        kgate(AX, AY, MA[3], 0);  kgate(BX, BY, MB[3], 0);
        kgate(AX, AY, MA[2], 1);  kgate(BX, BY, MB[2], 1);
        kgate(AX, AY, MA[1], 2);  kgate(BX, BY, MB[1], 2);
        pgate(AX, AY, MA[0]);     pgate(BX, BY, MB[0]);
        sgate(AX, AY, MA[10], 1, lane);  sgate(BX, BY, MB[10], 1, lane);
        sgate(AX, AY, MA[9], 2, lane);   sgate(BX, BY, MB[9], 2, lane);

        // transpose C -> T (sigma buffer); gather folds q8
        tr_scatter(AX, AY, bufA + b * 4096, stid);
        tr_scatter(BX, BY, bufB + b * 4096, stid);
        __syncthreads();
        tr_gather(AX, AY, bufA + b * 4096, MA[8], tid, gb4T);
        tr_gather(BX, BY, bufB + b * 4096, MB[8], tid, gb4T);
        b ^= 1;

        // T phase
        kgate(AX, AY, MA[6], 0);  kgate(BX, BY, MB[6], 0);
        kgate(AX, AY, MA[5], 1);  kgate(BX, BY, MB[5], 1);
        kgate(AX, AY, MA[4], 2);  kgate(BX, BY, MB[4], 2);
        pgate(AX, AY, MA[7]);     pgate(BX, BY, MB[7]);

        // perm RT (CZ on odd layers); gather folds next layer's q11
        if (l < 5) {
            unsigned cz = (unsigned)(l & 1);
            perm_scatter(AX, AY, bufA + b * 4096, dt, czm0, czm1, cz);
            perm_scatter(BX, BY, bufB + b * 4096, dt, czm0, czm1, cz);
            __syncthreads();
            float4 nA = ((l + 1) & 1) ? Mf[0][l >> 1][11] : Mraw[l][11];
            float4 nB = ((l + 1) & 1) ? Mf[1][l >> 1][11] : Mraw[l][11];
            perm_gather(AX, AY, bufA + b * 4096, nA, tid);
            perm_gather(BX, BY, bufB + b * 4096, nB, tid);
            b ^= 1;
        }
    }

    // ---- measurement (both samples); layer-5 perm folded into signs ----
    float z[6] = {0.f, 0.f, 0.f, 0.f, 0.f, 0.f};
    #pragma unroll
    for (int k = 0; k < 8; k++) {
        int d0 = dt ^ permdst(k << 5);
        int s11 = (d0 >> 11) & 1, s10 = (d0 >> 10) & 1, s9 = (d0 >> 9) & 1;
        u64 PA = f2(AY[k], AY[k], m2(AX[k], AX[k]));
        u64 PB = f2(BY[k], BY[k], m2(BX[k], BX[k]));
        float pla, pha, plb, phb;
        upk(PA, pla, pha); upk(PB, plb, phb);
        float suma = pla + pha, difa = pla - pha;
        float sumb = plb + phb, difb = plb - phb;
        z[0] += s11 ? -difa : difa;
        z[1] += s10 ? -suma : suma;
        z[2] += s9 ? -suma : suma;
        z[3] += s11 ? -difb : difb;
        z[4] += s10 ? -sumb : sumb;
        z[5] += s9 ? -sumb : sumb;
    }
    #pragma unroll
    for (int o = 16; o; o >>= 1) {
        #pragma unroll
        for (int j = 0; j < 6; j++) z[j] += __shfl_xor_sync(~0u, z[j], o);
    }
    if (lane == 0) {
        #pragma unroll
        for (int j = 0; j < 6; j++) wz[w][j] = z[j];
    }
    __syncthreads();
    if (tid < 6) {
        float t = 0.f;
        #pragma unroll
        for (int i = 0; i < 8; i++) t += wz[i][tid];
        qv[tid] = t;
    }
    __syncthreads();

    // ---- head for both samples ----
    if (tid < 64) {
        int s = tid >> 5, o = tid & 31;
        float acc = b4[o];
        acc = fmaf(W4[o * 3 + 0], qv[s * 3 + 0], acc);
        acc = fmaf(W4[o * 3 + 1], qv[s * 3 + 1], acc);
        acc = fmaf(W4[o * 3 + 2], qv[s * 3 + 2], acc);
        h4s[s][o] = gelu_f(acc);
    }
    __syncthreads();
    if (tid < 128) {
        int s = tid >> 6, o = tid & 63;
        const float* wr = W5 + o * 32;
        float acc = b5[o];
        #pragma unroll
        for (int j = 0; j < 32; j++) acc = fmaf(wr[j], h4s[s][j], acc);
        out[(2 * bidx + s) * 64 + o] = acc;
    }
}

extern "C" void kernel_launch(void* const* d_in, const int* in_sizes, int n_in,
                              void* d_out, int out_size)
{
    const float* x    = (const float*)d_in[0];
    const float* W1   = (const float*)d_in[1];
    const float* b1   = (const float*)d_in[2];
    const float* g_ln = (const float*)d_in[3];
    const float* b_ln = (const float*)d_in[4];
    const float* W2   = (const float*)d_in[5];
    const float* b2   = (const float*)d_in[6];
    const float* W3   = (const float*)d_in[7];
    const float* b3   = (const float*)d_in[8];
    const float* qw   = (const float*)d_in[9];
    const float* W4   = (const float*)d_in[10];
    const float* b4   = (const float*)d_in[11];
    const float* W5   = (const float*)d_in[12];
    const float* b5   = (const float*)d_in[13];

    const size_t shmem = 16384 * sizeof(float2);  // 128 KB: 2 samples x ping-pong
    cudaFuncSetAttribute(qpu_kernel, cudaFuncAttributeMaxDynamicSharedMemorySize,
                         (int)shmem);
    qpu_kernel<<<NB, TPB, shmem>>>(x, W1, b1, g_ln, b_ln, W2, b2, W3, b3, qw,
                                   W4, b4, W5, b5, (float*)d_out);
}

// round 12
// speedup vs baseline: 1.0513x; 1.0513x over previous
#include <cuda_runtime.h>
#include <math.h>

#define NQ 12
#define TPB 256
#define NB 256

typedef unsigned long long u64;

__device__ __forceinline__ u64 pk(float lo, float hi) {
    u64 r;
    asm("mov.b64 %0,{%1,%2};" : "=l"(r)
        : "r"(__float_as_uint(lo)), "r"(__float_as_uint(hi)));
    return r;
}
__device__ __forceinline__ void upk(u64 v, float& lo, float& hi) {
    unsigned a, b;
    asm("mov.b64 {%0,%1},%2;" : "=r"(a), "=r"(b) : "l"(v));
    lo = __uint_as_float(a); hi = __uint_as_float(b);
}
__device__ __forceinline__ u64 sp(float f) { return pk(f, f); }
__device__ __forceinline__ u64 f2(u64 a, u64 b, u64 c) {
    u64 d;
    asm("fma.rn.f32x2 %0,%1,%2,%3;" : "=l"(d) : "l"(a), "l"(b), "l"(c));
    return d;
}
__device__ __forceinline__ u64 m2(u64 a, u64 b) {
    u64 d;
    asm("mul.rn.f32x2 %0,%1,%2;" : "=l"(d) : "l"(a), "l"(b));
    return d;
}
__device__ __forceinline__ u64 swp(u64 v) {
    float l, h; upk(v, l, h); return pk(h, l);
}

__device__ __forceinline__ float2 cmulc(float2 x, float2 y) {
    return make_float2(x.x * y.x - x.y * y.y, x.x * y.y + x.y * y.x);
}

__device__ __forceinline__ float gelu_f(float x) {
    return 0.5f * x * (1.0f + erff(x * 0.7071067811865476f));
}

// Composed CNOT-ring permutation (CNOT(0,1)..CNOT(10,11),CNOT(11,0)).
// Qubit w lives at bit position (11-w). LINEAR over GF(2).
__device__ __forceinline__ int permdst(int idx) {
    int y = idx;
    y ^= y >> 1; y ^= y >> 2; y ^= y >> 4; y ^= y >> 8;
    return (y & 0x7FF) | (((y ^ (idx >> 11)) & 1) << 11);
}

// ---- symmetric-form gates: float4 m = (U0.x,U0.y,U1.x,U1.y),
//      U11 = conj(U00), U10 = (-U01.x, U01.y). Survives the RY fold. ----

__device__ __forceinline__ void kgate(u64* SX, u64* SY, float4 m, int rb)
{
    u64 g0x = sp(m.x),  g0y = sp(m.y), g0yn = sp(-m.y);
    u64 g1x = sp(m.z),  g1xn = sp(-m.z);
    u64 g1y = sp(m.w),  g1yn = sp(-m.w);
    #pragma unroll
    for (int k = 0; k < 8; k++) {
        if (!((k >> rb) & 1)) {
            const int k1 = k | (1 << rb);
            u64 X0 = SX[k], Y0 = SY[k], X1 = SX[k1], Y1 = SY[k1];
            SX[k]  = f2(g1yn, Y1, f2(g1x, X1, f2(g0yn, Y0, m2(g0x, X0))));
            SY[k]  = f2(g1y,  X1, f2(g1x, Y1, f2(g0y,  X0, m2(g0x, Y0))));
            SX[k1] = f2(g0y,  Y1, f2(g0x, X1, f2(g1yn, Y0, m2(g1xn, X0))));
            SY[k1] = f2(g0yn, X1, f2(g0x, Y1, f2(g1y,  X0, m2(g1xn, Y0))));
        }
    }
}

__device__ __forceinline__ void pgate(u64* SX, u64* SY, float4 m)
{
    u64 Dx  = sp(m.x);
    u64 Dy  = pk(m.y, -m.y), Dyn = pk(-m.y, m.y);
    u64 Ox  = pk(m.z, -m.z);
    u64 Oy  = sp(m.w), Oyn = sp(-m.w);
    #pragma unroll
    for (int k = 0; k < 8; k++) {
        u64 sX = swp(SX[k]), sY = swp(SY[k]);
        u64 nX = f2(Oyn, sY, f2(Ox, sX, f2(Dyn, SY[k], m2(Dx, SX[k]))));
        u64 nY = f2(Oy,  sX, f2(Ox, sY, f2(Dy,  SX[k], m2(Dx, SY[k]))));
        SX[k] = nX; SY[k] = nY;
    }
}

__device__ __forceinline__ void sgate(u64* SX, u64* SY, float4 m, int p, int lane)
{
    const int sb = (lane >> p) & 1;
    float dY = sb ? -m.y : m.y;
    float oX = sb ? -m.z : m.z;
    u64 gdx = sp(m.x), gdy = sp(dY), gdyn = sp(-dY);
    u64 gox = sp(oX),  goy = sp(m.w), goyn = sp(-m.w);
    #pragma unroll
    for (int k = 0; k < 8; k++) {
        float xl, xh, yl, yh;
        upk(SX[k], xl, xh); upk(SY[k], yl, yh);
        float oxl = __shfl_xor_sync(~0u, xl, 1 << p);
        float oxh = __shfl_xor_sync(~0u, xh, 1 << p);
        float oyl = __shfl_xor_sync(~0u, yl, 1 << p);
        float oyh = __shfl_xor_sync(~0u, yh, 1 << p);
        u64 OX = pk(oxl, oxh), OY = pk(oyl, oyh);
        u64 nX = f2(goyn, OY, f2(gox, OX, f2(gdyn, SY[k], m2(gdx, SX[k]))));
        u64 nY = f2(goy,  OX, f2(gox, OY, f2(gdy,  SX[k], m2(gdx, SY[k]))));
        SX[k] = nX; SY[k] = nY;
    }
}

__global__ void __launch_bounds__(TPB, 2)
qpu_kernel(const float* __restrict__ x,
           const float* __restrict__ W1, const float* __restrict__ b1,
           const float* __restrict__ g_ln, const float* __restrict__ b_ln,
           const float* __restrict__ W2, const float* __restrict__ b2,
           const float* __restrict__ W3, const float* __restrict__ b3,
           const float* __restrict__ qw,
           const float* __restrict__ W4, const float* __restrict__ b4,
           const float* __restrict__ W5, const float* __restrict__ b5,
           float* __restrict__ out)
{
    // dynamic: 2 ping-pong float2 buffers, 4096 each = 64 KB
    extern __shared__ float2 fsm[];
    __shared__ __align__(16) float xrow[256];
    __shared__ __align__(16) float h1s[128];
    __shared__ __align__(16) float hns[128];
    __shared__ __align__(16) float h2s[64];
    __shared__ float4 Mm[5][NQ];          // merged gates (U0.x,U0.y,U1.x,U1.y)
    __shared__ float2 v0s[NQ], v1s[NQ];   // initial per-qubit product-state vectors
    __shared__ float cqs[NQ], sqs[NQ];    // re-upload RY half-angle cos/sin
    __shared__ float red0[8], red1[8];
    __shared__ float wz[8][3];
    __shared__ float qv[3];
    __shared__ float h4s[32];

    const int tid = threadIdx.x;
    const int bidx = blockIdx.x;
    const int lane = tid & 31, w = tid >> 5;

    xrow[tid] = x[bidx * 256 + tid];
    __syncthreads();

    // ---- h1 = gelu(x @ W1^T + b1), 128 outputs; overlap: raw gate tables ----
    if (tid < 128) {
        const float4* wr = (const float4*)(W1 + tid * 256);
        const float4* xr = (const float4*)xrow;
        float acc0 = 0.f, acc1 = 0.f;
        #pragma unroll 8
        for (int k = 0; k < 64; k += 2) {
            float4 wv = wr[k], xv = xr[k];
            acc0 = fmaf(wv.x, xv.x, acc0); acc0 = fmaf(wv.y, xv.y, acc0);
            acc0 = fmaf(wv.z, xv.z, acc0); acc0 = fmaf(wv.w, xv.w, acc0);
            float4 w2_ = wr[k + 1], xv2 = xr[k + 1];
            acc1 = fmaf(w2_.x, xv2.x, acc1); acc1 = fmaf(w2_.y, xv2.y, acc1);
            acc1 = fmaf(w2_.z, xv2.z, acc1); acc1 = fmaf(w2_.w, xv2.w, acc1);
        }
        h1s[tid] = gelu_f(acc0 + acc1 + b1[tid]);
    } else if (tid < 188) {
        // raw (unfolded) gate matrices for layers 1..5, symmetric form
        int idx = tid - 128;                 // 0..59
        int L = idx / 12 + 1, q = idx - (L - 1) * 12;
        const float* wp = qw + (L * NQ + q) * 3;
        float w0 = wp[0], w1 = wp[1], w2v = wp[2];
        float sh, ch; sincosf(0.5f * w1, &sh, &ch);
        float sa, ca; sincosf(0.5f * (w0 + w2v), &sa, &ca);
        float sb, cb; sincosf(0.5f * (w0 - w2v), &sb, &cb);
        Mm[L - 1][q] = make_float4(ch * ca, -ch * sa, -sh * cb, -sh * sb);
    }
    __syncthreads();

    // ---- layernorm over 128 (all threads compute stats; 1 barrier saved) ----
    {
        float v = (tid < 128) ? h1s[tid] : 0.f;
        float s = v, ss = v * v;
        #pragma unroll
        for (int o = 16; o; o >>= 1) {
            s += __shfl_xor_sync(~0u, s, o);
            ss += __shfl_xor_sync(~0u, ss, o);
        }
        if (lane == 0) { red0[w] = s; red1[w] = ss; }
    }
    __syncthreads();
    if (tid < 128) {
        float s = 0.f, ss = 0.f;
        #pragma unroll
        for (int i = 0; i < 8; i++) { s += red0[i]; ss += red1[i]; }
        float mu = s * (1.f / 128.f);
        float var = ss * (1.f / 128.f) - mu * mu;
        float rstd = rsqrtf(var + 1e-5f);
        hns[tid] = (h1s[tid] - mu) * rstd * g_ln[tid] + b_ln[tid];
    }
    __syncthreads();

    // ---- h2 = gelu(hn @ W2^T + b2), 64 outputs ----
    if (tid < 64) {
        const float4* wr = (const float4*)(W2 + tid * 128);
        const float4* hr = (const float4*)hns;
        float acc = 0.f;
        #pragma unroll 8
        for (int k = 0; k < 32; k++) {
            float4 wv = wr[k], hv = hr[k];
            acc = fmaf(wv.x, hv.x, acc); acc = fmaf(wv.y, hv.y, acc);
            acc = fmaf(wv.z, hv.z, acc); acc = fmaf(wv.w, hv.w, acc);
        }
        h2s[tid] = gelu_f(acc + b2[tid]);
    }
    __syncthreads();

    // ---- xq = tanh(h2 @ W3^T + b3); enc = xq*pi^2; init vectors + re-upload cs ----
    if (tid < NQ) {
        const float* wr = W3 + tid * 64;
        float acc = 0.f;
        #pragma unroll
        for (int k = 0; k < 64; k++) acc = fmaf(wr[k], h2s[k], acc);
        float xqv = tanhf(acc + b3[tid]);
        float e = xqv * 9.869604401089358f;   // pi^2
        float se, ce; sincosf(0.5f * e, &se, &ce);
        const float* wp = qw + tid * 3;
        float w0 = wp[0], w1 = wp[1], w2v = wp[2];
        float sh, ch; sincosf(0.5f * w1, &sh, &ch);
        float sa, ca; sincosf(0.5f * (w0 + w2v), &sa, &ca);
        float sb, cb; sincosf(0.5f * (w0 - w2v), &sb, &cb);
        float2 u00 = make_float2(ch * ca, -ch * sa);
        float2 u01 = make_float2(-sh * cb, -sh * sb);
        float2 u10 = make_float2(sh * cb, -sh * sb);
        float2 u11 = make_float2(ch * ca, ch * sa);
        v0s[tid] = make_float2(u00.x * ce + u01.x * se, u00.y * ce + u01.y * se);
        v1s[tid] = make_float2(u10.x * ce + u11.x * se, u10.y * ce + u11.y * se);
        float s4, c4; sincosf(0.25f * e, &s4, &c4);
        cqs[tid] = c4; sqs[tid] = s4;
    }
    __syncthreads();

    // ---- fold RY(enc/2) re-upload into odd layers (L = 1,3,5) ----
    // NOTE: no barrier needed after this block — all consumers of Mm read it
    // only AFTER the first RT's internal __syncthreads below.
    if (tid < 36) {
        int L = 1 + 2 * (tid / 12), q = tid % 12;
        float4 m = Mm[L - 1][q];
        float cf = cqs[q], sf = sqs[q];
        Mm[L - 1][q] = make_float4(m.x * cf + m.z * sf,  m.y * cf + m.w * sf,
                                   -m.x * sf + m.z * cf, -m.y * sf + m.w * cf);
    }

    // ============ statevector ============
    // Canonical C: SX[k]/SY[k] hold idx (k<<8)|tid (lo) and |0x800 (hi).
    // Transposed T: SX[k]/SY[k] hold idx tb|(k<<5) (lo) and |0x10 (hi), with
    //   tb = (tid&0xF) | ((tid>>5)<<8) | (((tid>>4)&1)<<11).
    // Transpose buffer uses sigma = swap(bit0, bit3) so the q8 partner is
    //   address-adjacent (float4-gatherable).
    u64 SX[8], SY[8];
    const int tb = (tid & 0xF) | ((tid >> 5) << 8) | (((tid >> 4) & 1) << 11);
    const int dt = permdst(tb);   // per-thread part of the linear perm
    const int stid = (tid & ~9) | ((tid & 1) << 3) | ((tid >> 3) & 1); // sigma(tid low4)
    const int sgtb = (tb & ~9) | ((tb & 1) << 3) | ((tb >> 3) & 1);    // sigma(tb)
    const int gb4T = (sgtb & ~1) >> 1;   // float4 base for transpose gather

    // precomputed CZ sign masks: bit k = sign for dst of (lo / hi) element k
    unsigned czm0 = 0, czm1 = 0;
    #pragma unroll
    for (int k = 0; k < 8; k++) {
        int d0 = dt ^ permdst(k << 5);   // permdst(k<<5) folds to a constant
        int d1 = d0 ^ 0x81F;             // pack-partner dst (flip idx bit 4)
        czm0 |= ((unsigned)__popc((d0 & (d0 >> 2)) & 0x2AA) & 1u) << k;
        czm1 |= ((unsigned)__popc((d1 & (d1 >> 2)) & 0x2AA) & 1u) << k;
    }

    // ---- init product state directly in T layout (layer-0 gates folded) ----
    {
        float2 cm = (tid & 1) ? v1s[11] : v0s[11];
        cm = cmulc(cm, (tid & 2) ? v1s[10] : v0s[10]);
        cm = cmulc(cm, (tid & 4) ? v1s[9] : v0s[9]);
        cm = cmulc(cm, (tid & 8) ? v1s[8] : v0s[8]);
        cm = cmulc(cm, ((tid >> 4) & 1) ? v1s[0] : v0s[0]);
        cm = cmulc(cm, ((tid >> 5) & 1) ? v1s[3] : v0s[3]);
        cm = cmulc(cm, ((tid >> 6) & 1) ? v1s[2] : v0s[2]);
        cm = cmulc(cm, ((tid >> 7) & 1) ? v1s[1] : v0s[1]);
        float2 q7a = v0s[7], q7b = v1s[7];
        #pragma unroll
        for (int k = 0; k < 8; k++) {
            float2 a = cm;
            a = cmulc(a, (k & 1) ? v1s[6] : v0s[6]);
            a = cmulc(a, (k & 2) ? v1s[5] : v0s[5]);
            a = cmulc(a, (k & 4) ? v1s[4] : v0s[4]);
            float2 lo = cmulc(a, q7a);
            float2 hi = cmulc(a, q7b);
            SX[k] = pk(lo.x, hi.x);
            SY[k] = pk(lo.y, hi.y);
        }
    }

    int b = 0;

    // ---- perm RT from T -> C. Scatter applies CNOT ring; CZ signs only when
    //      CZSEL != 0 (uniform branch — no sign ops on layers 0/2/4). Gather
    //      applies the NEXT layer's qubit-11 gate via float4 loads. ----
    #define RT_PERM(CZSEL, MN)                                                 \
    {                                                                          \
        float2* fb = fsm + b * 4096;                                           \
        if (CZSEL) {                                                           \
            _Pragma("unroll")                                                  \
            for (int k = 0; k < 8; k++) {                                      \
                int d0 = dt ^ permdst(k << 5);                                 \
                float xl, xh, yl, yh;                                          \
                upk(SX[k], xl, xh); upk(SY[k], yl, yh);                        \
                unsigned g0 = ((czm0 >> k) & 1u) << 31;                        \
                unsigned g1 = ((czm1 >> k) & 1u) << 31;                        \
                xl = __uint_as_float(__float_as_uint(xl) ^ g0);                \
                yl = __uint_as_float(__float_as_uint(yl) ^ g0);                \
                xh = __uint_as_float(__float_as_uint(xh) ^ g1);                \
                yh = __uint_as_float(__float_as_uint(yh) ^ g1);                \
                fb[d0] = make_float2(xl, yl);                                  \
                fb[d0 ^ 0x81F] = make_float2(xh, yh);                          \
            }                                                                  \
        } else {                                                               \
            _Pragma("unroll")                                                  \
            for (int k = 0; k < 8; k++) {                                      \
                int d0 = dt ^ permdst(k << 5);                                 \
                float xl, xh, yl, yh;                                          \
                upk(SX[k], xl, xh); upk(SY[k], yl, yh);                        \
                fb[d0] = make_float2(xl, yl);                                  \
                fb[d0 ^ 0x81F] = make_float2(xh, yh);                          \
            }                                                                  \
        }                                                                      \
        __syncthreads();                                                       \
        {                                                                      \
            const float4 mg = (MN);                                            \
            const int sbq = tid & 1;                                           \
            float dyv = sbq ? -mg.y : mg.y;                                    \
            float oxv = sbq ? -mg.z : mg.z;                                    \
            float2 gd = make_float2(mg.x, dyv);                                \
            float2 go = make_float2(oxv, mg.w);                                \
            float2 Cl = sbq ? go : gd;                                         \
            float2 Ch = sbq ? gd : go;                                         \
            u64 clr = sp(Cl.x), cli = sp(Cl.y), cln = sp(-Cl.y);               \
            u64 chr = sp(Ch.x), chi_ = sp(Ch.y), chn = sp(-Ch.y);              \
            const float4* F4 = (const float4*)fb;                              \
            const int gbase = tid >> 1;                                        \
            _Pragma("unroll")                                                  \
            for (int k = 0; k < 8; k++) {                                      \
                int i4 = (k << 7) | gbase;                                     \
                float4 va = F4[i4];                                            \
                float4 vb = F4[i4 | 0x400];                                    \
                u64 Xl = pk(va.x, vb.x), Yl = pk(va.y, vb.y);                  \
                u64 Xh = pk(va.z, vb.z), Yh = pk(va.w, vb.w);                  \
                SX[k] = f2(chn, Yh, f2(chr, Xh, f2(cln, Yl, m2(clr, Xl))));    \
                SY[k] = f2(chi_, Xh, f2(chr, Yh, f2(cli, Xl, m2(clr, Yl))));   \
            }                                                                  \
        }                                                                      \
        b ^= 1;                                                                \
    }

    // layer-0 CNOT ring (no CZ); gather applies layer-1 qubit-11 gate
    RT_PERM(0, Mm[0][11])

    // ---- layers 1..5 ----
    for (int l = 1; l < 6; l++) {
        const float4* M = Mm[l - 1];

        // C phase: q11 done at perm gather. kgates q3,q2,q1; pgate q0;
        // sgates q10,q9 (lane bits 1,2). q8 folds into the transpose gather.
        kgate(SX, SY, M[3], 0);
        kgate(SX, SY, M[2], 1);
        kgate(SX, SY, M[1], 2);
        pgate(SX, SY, M[0]);
        sgate(SX, SY, M[10], 1, lane);
        sgate(SX, SY, M[9], 2, lane);

        // transpose C -> T (sigma-swizzled buffer); gather applies q8 on read
        // via float4 loads (q8 partner adjacent under sigma).
        {
            float2* fb = fsm + b * 4096;
            #pragma unroll
            for (int k = 0; k < 8; k++) {
                int s0 = (k << 8) | stid;
                float xl, xh, yl, yh;
                upk(SX[k], xl, xh); upk(SY[k], yl, yh);
                fb[s0] = make_float2(xl, yl);
                fb[s0 | 0x800] = make_float2(xh, yh);
            }
            __syncthreads();
            const float4 mg = M[8];
            const int sbq = (tid >> 3) & 1;
            float dyv = sbq ? -mg.y : mg.y;
            float oxv = sbq ? -mg.z : mg.z;
            float2 gd = make_float2(mg.x, dyv);
            float2 go = make_float2(oxv, mg.w);
            float2 Cl = sbq ? go : gd;
            float2 Ch = sbq ? gd : go;
            u64 clr = sp(Cl.x), cli = sp(Cl.y), cln = sp(-Cl.y);
            u64 chr = sp(Ch.x), chi_ = sp(Ch.y), chn = sp(-Ch.y);
            const float4* F4 = (const float4*)fb;
            #pragma unroll
            for (int k = 0; k < 8; k++) {
                int i4 = (k << 4) | gb4T;
                float4 va = F4[i4];        // pack-lo: (lo-side amp, hi-side amp)
                float4 vb = F4[i4 + 8];    // pack-hi (idx bit 4)
                u64 Xl = pk(va.x, vb.x), Yl = pk(va.y, vb.y);
                u64 Xh = pk(va.z, vb.z), Yh = pk(va.w, vb.w);
                SX[k] = f2(chn, Yh, f2(chr, Xh, f2(cln, Yl, m2(clr, Xl))));
                SY[k] = f2(chi_, Xh, f2(chr, Yh, f2(cli, Xl, m2(clr, Yl))));
            }
            b ^= 1;
        }

        // T phase: kgates q6,q5,q4 (idx bits 5,6,7); pgate q7 (T pack = idx b4)
        kgate(SX, SY, M[6], 0);
        kgate(SX, SY, M[5], 1);
        kgate(SX, SY, M[4], 2);
        pgate(SX, SY, M[7]);

        // perm RT back to C (CZ on odd layers); gather applies next layer's
        // q11. Layer 5's perm folds into the measurement.
        if (l < 5) RT_PERM((l & 1), Mm[l][11])
    }
    #undef RT_PERM

    // ---- measurement from T layout; layer-5 perm folded into signs ----
    // pack partner dst = d0 ^ 0x81F: flips d11, keeps d10/d9.
    float z0 = 0.f, z1 = 0.f, z2 = 0.f;
    #pragma unroll
    for (int k = 0; k < 8; k++) {
        int d0 = dt ^ permdst(k << 5);
        u64 P = f2(SY[k], SY[k], m2(SX[k], SX[k]));
        float pl, ph; upk(P, pl, ph);
        float sum = pl + ph, dif = pl - ph;
        z0 += ((d0 >> 11) & 1) ? -dif : dif;
        z1 += ((d0 >> 10) & 1) ? -sum : sum;
        z2 += ((d0 >> 9) & 1) ? -sum : sum;
    }
    #pragma unroll
    for (int o = 16; o; o >>= 1) {
        z0 += __shfl_xor_sync(~0u, z0, o);
        z1 += __shfl_xor_sync(~0u, z1, o);
        z2 += __shfl_xor_sync(~0u, z2, o);
    }
    if (lane == 0) { wz[w][0] = z0; wz[w][1] = z1; wz[w][2] = z2; }
    __syncthreads();
    if (tid < 3) {
        float t = 0.f;
        #pragma unroll
        for (int i = 0; i < 8; i++) t += wz[i][tid];
        qv[tid] = t;
    }
    __syncthreads();

    // ---- head: gelu(q @ W4^T + b4) @ W5^T + b5 ----
    if (tid < 32) {
        float acc = b4[tid];
        acc = fmaf(W4[tid * 3 + 0], qv[0], acc);
        acc = fmaf(W4[tid * 3 + 1], qv[1], acc);
        acc = fmaf(W4[tid * 3 + 2], qv[2], acc);
        h4s[tid] = gelu_f(acc);
    }
    __syncthreads();
    if (tid < 64) {
        const float* wr = W5 + tid * 32;
        float acc = b5[tid];
        #pragma unroll
        for (int j = 0; j < 32; j++) acc = fmaf(wr[j], h4s[j], acc);
        out[bidx * 64 + tid] = acc;
    }
}

extern "C" void kernel_launch(void* const* d_in, const int* in_sizes, int n_in,
                              void* d_out, int out_size)
{
    const float* x    = (const float*)d_in[0];
    const float* W1   = (const float*)d_in[1];
    const float* b1   = (const float*)d_in[2];
    const float* g_ln = (const float*)d_in[3];
    const float* b_ln = (const float*)d_in[4];
    const float* W2   = (const float*)d_in[5];
    const float* b2   = (const float*)d_in[6];
    const float* W3   = (const float*)d_in[7];
    const float* b3   = (const float*)d_in[8];
    const float* qw   = (const float*)d_in[9];
    const float* W4   = (const float*)d_in[10];
    const float* b4   = (const float*)d_in[11];
    const float* W5   = (const float*)d_in[12];
    const float* b5   = (const float*)d_in[13];

    const size_t shmem = 8192 * sizeof(float2);  // 64 KB: 2 ping-pong buffers
    cudaFuncSetAttribute(qpu_kernel, cudaFuncAttributeMaxDynamicSharedMemorySize,
                         (int)shmem);
    qpu_kernel<<<NB, TPB, shmem>>>(x, W1, b1, g_ln, b_ln, W2, b2, W3, b3, qw,
                                   W4, b4, W5, b5, (float*)d_out);
}